// round 14
// baseline (speedup 1.0000x reference)
#include <cuda_runtime.h>
#include <cuda_bf16.h>
#include <cuda_fp16.h>
#include <cstdint>

// Problem constants
#define NPTS   1000000
#define FEAT   32
#define RES_H  512
#define RES_W  128
#define TSTEP  (1.0f/256.0f)   // 1/(2*RES_W), exactly representable
// XLA rewrites (-pts / 1.6f) as (-pts * (1/1.6f)); 1/1.6f rounds to exactly 0.625f.
#define INV_BOUNDS 0.625f

// Transposed fp16 planes: [plane][h][w][f] — 3*512*128*32*2 = 12.6 MB, L2-resident.
__device__ __half g_T16[3 * RES_H * RES_W * FEAT];

// ---------------------------------------------------------------------------
// Kernel 1: transpose+convert each plane [F,H,W] fp32 -> [H,W,F] fp16.
// One block per (plane, h): 1536 blocks x 256 threads. Fires the PDL trigger
// as soon as its global writes are issued.
// ---------------------------------------------------------------------------
__global__ void __launch_bounds__(256)
transpose_planes(const float* __restrict__ p0,
                 const float* __restrict__ p1,
                 const float* __restrict__ p2) {
    __shared__ float tile[32][129];
    int b   = blockIdx.x;
    int h   = b & 511;
    int pl  = b >> 9;
    const float* src = (pl == 0) ? p0 : ((pl == 1) ? p1 : p2);
    int tid = threadIdx.x;

    #pragma unroll
    for (int k = 0; k < 16; k++) {
        int idx = tid + 256 * k;
        int f = idx >> 7;
        int w = idx & 127;
        tile[f][w] = src[f * (RES_H * RES_W) + h * RES_W + w];
    }
    __syncthreads();

    __half2* dst = reinterpret_cast<__half2*>(g_T16) + (size_t)(pl * RES_H + h) * (RES_W * FEAT / 2);
    #pragma unroll
    for (int k = 0; k < 8; k++) {
        int idx2 = tid + 256 * k;
        int w  = idx2 >> 4;
        int fp = idx2 & 15;
        dst[idx2] = __floats2half2_rn(tile[2 * fp][w], tile[2 * fp + 1][w]);
    }
    // Allow the dependent (main) kernel to start launching.
    cudaTriggerProgrammaticLaunchCompletion();
}

// ---------------------------------------------------------------------------
// Index math: IEEE round-to-nearest ops, round-half-even conversion.
// ---------------------------------------------------------------------------
__device__ __forceinline__ int idx_w(float c) {
    float v = __fmul_rn(__fmul_rn(__fadd_rn(c, 1.0f), 0.5f), 127.0f);
    int k = __float2int_rn(v);
    return min(127, max(0, k));
}
__device__ __forceinline__ int idx_h(float c) {
    float v = __fmul_rn(__fmul_rn(__fadd_rn(c, 1.0f), 0.5f), 511.0f);
    int k = __float2int_rn(v);
    return min(511, max(0, k));
}

__device__ __forceinline__ void gather_addrs(float t, float px, float py, float pz,
                                             int sub, unsigned& c0, unsigned& c1, unsigned& c2) {
    int ix  = idx_w(t);
    c0 = (unsigned)(((0 * RES_H + idx_h(px)) * RES_W + ix) * (FEAT / 4)) + sub;
    c1 = (unsigned)(((1 * RES_H + idx_h(py)) * RES_W + ix) * (FEAT / 4)) + sub;
    c2 = (unsigned)(((2 * RES_H + idx_h(pz)) * RES_W + ix) * (FEAT / 4)) + sub;
}

// Gather load with evict_last L2 policy: pins the 12.6MB plane scratch in L2
// against the normal-priority output write stream.
__device__ __forceinline__ uint2 ldg_el(const uint2* p, uint64_t pol) {
    uint2 v;
    asm volatile("ld.global.nc.L2::cache_hint.v2.u32 {%0,%1}, [%2], %3;"
                 : "=r"(v.x), "=r"(v.y) : "l"(p), "l"(pol));
    return v;
}

__device__ __forceinline__ float4 prod3(uint2 ua, uint2 ub, uint2 uc) {
    float2 a0 = __half22float2(*reinterpret_cast<__half2*>(&ua.x));
    float2 a1 = __half22float2(*reinterpret_cast<__half2*>(&ua.y));
    float2 b0 = __half22float2(*reinterpret_cast<__half2*>(&ub.x));
    float2 b1 = __half22float2(*reinterpret_cast<__half2*>(&ub.y));
    float2 c0f = __half22float2(*reinterpret_cast<__half2*>(&uc.x));
    float2 c1f = __half22float2(*reinterpret_cast<__half2*>(&uc.y));
    float4 r;
    r.x = __fmul_rn(__fmul_rn(a0.x, b0.x), c0f.x);
    r.y = __fmul_rn(__fmul_rn(a0.y, b0.y), c0f.y);
    r.z = __fmul_rn(__fmul_rn(a1.x, b1.x), c1f.x);
    r.w = __fmul_rn(__fmul_rn(a1.y, b1.y), c1f.y);
    return r;
}

// ---------------------------------------------------------------------------
// Kernel 2: gather + product + dual write. Block = 256 threads = 64 points,
// 2 pts/thread (MLP 6). Staging + index math before the PDL grid-sync.
// Output stores at evict_normal priority -> L2 acts as an elastic write
// buffer so DRAM drain overlaps compute and the next replay's transpose.
// ---------------------------------------------------------------------------
__global__ void __launch_bounds__(256)
displacement_kernel(const float* __restrict__ pts,
                    const float* __restrict__ tim,
                    float* __restrict__ out) {
    __shared__ float s_p[192];  // pts for 64 points
    __shared__ float s_t[64];   // tim for 64 points

    int tid  = threadIdx.x;
    int base = blockIdx.x * 64;

    if (tid < 192)  s_p[tid]       = pts[base * 3 + tid];
    else            s_t[tid - 192] = tim[base + (tid - 192)];
    __syncthreads();

    int il  = tid >> 3;      // local point 0..31 (pair partner: il+32)
    int sub = tid & 7;
    int jl  = il + 32;
    int i0  = base + il;
    int i1  = base + jl;     // only i1 can be NPTS-1

    float t0  = __fadd_rn(__fmul_rn(s_t[il], 2.0f), -1.0f);
    float px0 = __fmul_rn(-s_p[3 * il + 0], INV_BOUNDS);
    float py0 = __fmul_rn(-s_p[3 * il + 1], INV_BOUNDS);
    float pz0 = __fmul_rn(-s_p[3 * il + 2], INV_BOUNDS);
    float t1  = __fadd_rn(__fmul_rn(s_t[jl], 2.0f), -1.0f);
    float px1 = __fmul_rn(-s_p[3 * jl + 0], INV_BOUNDS);
    float py1 = __fmul_rn(-s_p[3 * jl + 1], INV_BOUNDS);
    float pz1 = __fmul_rn(-s_p[3 * jl + 2], INV_BOUNDS);

    unsigned a0, a1, a2, b0, b1, b2;
    gather_addrs(t0, px0, py0, pz0, sub, a0, a1, a2);
    gather_addrs(t1, px1, py1, pz1, sub, b0, b1, b2);

    uint64_t pol;
    asm("createpolicy.fractional.L2::evict_last.b64 %0, 1.0;" : "=l"(pol));

    // Wait for the transpose's global writes to be visible, then gather.
    cudaGridDependencySynchronize();

    const uint2* gbase = reinterpret_cast<const uint2*>(g_T16);
    uint2 va0 = ldg_el(gbase + a0, pol);
    uint2 va1 = ldg_el(gbase + a1, pol);
    uint2 va2 = ldg_el(gbase + a2, pol);
    uint2 vb0 = ldg_el(gbase + b0, pol);
    uint2 vb1 = ldg_el(gbase + b1, pol);
    uint2 vb2 = ldg_el(gbase + b2, pol);

    float4 r0 = prod3(va0, va1, va2);
    float4 r1 = prod3(vb0, vb1, vb2);
    float4 r1A = r1, r1B = r1;

    if (i1 == NPTS - 1) {
        // data_shift subtracts TSTEP from ALL 4 components of the last row only
        unsigned s0, s1, s2;
        gather_addrs(__fadd_rn(t1, -TSTEP), __fadd_rn(px1, -TSTEP),
                     __fadd_rn(py1, -TSTEP), __fadd_rn(pz1, -TSTEP), sub, s0, s1, s2);
        float4 r2 = prod3(ldg_el(gbase + s0, pol), ldg_el(gbase + s1, pol),
                          ldg_el(gbase + s2, pol));
        bool cond = __fadd_rn(px1, TSTEP) > 1.0f;   // data[-1,0] + TIME_STEP > 1.0
        r1A = cond ? r2 : r1;
        r1B = cond ? r1 : r2;
    }

    // feature_A at [0, N*F), feature_B at [N*F, 2*N*F). Plain stores
    // (evict_normal) — L2 buffers the write burst; scratch is pinned by
    // the evict_last load policy above.
    float4* o = reinterpret_cast<float4*>(out);
    size_t row0 = (size_t)i0 * 8 + sub;
    size_t row1 = (size_t)i1 * 8 + sub;
    o[row0] = r0;
    o[row1] = r1A;
    o[(size_t)NPTS * 8 + row0] = r0;
    o[(size_t)NPTS * 8 + row1] = r1B;
}

extern "C" void kernel_launch(void* const* d_in, const int* in_sizes, int n_in,
                              void* d_out, int out_size) {
    const float* pts  = (const float*)d_in[0];
    const float* tim  = (const float*)d_in[1];
    const float* p0   = (const float*)d_in[2];
    const float* p1   = (const float*)d_in[3];
    const float* p2   = (const float*)d_in[4];
    float* out = (float*)d_out;

    // 1) transpose+convert planes to [H,W,F] fp16 (1 block per plane-row)
    transpose_planes<<<3 * RES_H, 256>>>(p0, p1, p2);

    // 2) main kernel launched with PDL so its launch+preamble overlap the
    //    transpose tail; it grid-syncs before touching g_T16.
    cudaLaunchAttribute attrs[1];
    attrs[0].id = cudaLaunchAttributeProgrammaticStreamSerialization;
    attrs[0].val.programmaticStreamSerializationAllowed = 1;

    cudaLaunchConfig_t cfg = {};
    cfg.gridDim  = dim3(NPTS / 64);
    cfg.blockDim = dim3(256);
    cfg.dynamicSmemBytes = 0;
    cfg.stream = 0;
    cfg.attrs = attrs;
    cfg.numAttrs = 1;
    cudaLaunchKernelEx(&cfg, displacement_kernel, pts, tim, out);
}

// round 15
// speedup vs baseline: 1.0345x; 1.0345x over previous
#include <cuda_runtime.h>
#include <cuda_bf16.h>
#include <cuda_fp16.h>
#include <cstdint>

// Problem constants
#define NPTS   1000000
#define FEAT   32
#define RES_H  512
#define RES_W  128
#define TSTEP  (1.0f/256.0f)   // 1/(2*RES_W), exactly representable
// XLA rewrites (-pts / 1.6f) as (-pts * (1/1.6f)); 1/1.6f rounds to exactly 0.625f.
#define INV_BOUNDS 0.625f

// Transposed fp16 planes: [plane][h][w][f] — 3*512*128*32*2 = 12.6 MB, L2-resident.
__device__ __half g_T16[3 * RES_H * RES_W * FEAT];

// ---------------------------------------------------------------------------
// Kernel 1: transpose+convert each plane [F,H,W] fp32 -> [H,W,F] fp16.
// One block per (plane, h): 1536 blocks x 256 threads. Fires the PDL trigger
// as soon as its global writes are issued.
// ---------------------------------------------------------------------------
__global__ void __launch_bounds__(256)
transpose_planes(const float* __restrict__ p0,
                 const float* __restrict__ p1,
                 const float* __restrict__ p2) {
    __shared__ float tile[32][129];
    int b   = blockIdx.x;
    int h   = b & 511;
    int pl  = b >> 9;
    const float* src = (pl == 0) ? p0 : ((pl == 1) ? p1 : p2);
    int tid = threadIdx.x;

    #pragma unroll
    for (int k = 0; k < 16; k++) {
        int idx = tid + 256 * k;
        int f = idx >> 7;
        int w = idx & 127;
        tile[f][w] = src[f * (RES_H * RES_W) + h * RES_W + w];
    }
    __syncthreads();

    __half2* dst = reinterpret_cast<__half2*>(g_T16) + (size_t)(pl * RES_H + h) * (RES_W * FEAT / 2);
    #pragma unroll
    for (int k = 0; k < 8; k++) {
        int idx2 = tid + 256 * k;
        int w  = idx2 >> 4;
        int fp = idx2 & 15;
        dst[idx2] = __floats2half2_rn(tile[2 * fp][w], tile[2 * fp + 1][w]);
    }
    // Allow the dependent (main) kernel to start launching.
    cudaTriggerProgrammaticLaunchCompletion();
}

// ---------------------------------------------------------------------------
// Index math: IEEE round-to-nearest ops, round-half-even conversion.
// ---------------------------------------------------------------------------
__device__ __forceinline__ int idx_w(float c) {
    float v = __fmul_rn(__fmul_rn(__fadd_rn(c, 1.0f), 0.5f), 127.0f);
    int k = __float2int_rn(v);
    return min(127, max(0, k));
}
__device__ __forceinline__ int idx_h(float c) {
    float v = __fmul_rn(__fmul_rn(__fadd_rn(c, 1.0f), 0.5f), 511.0f);
    int k = __float2int_rn(v);
    return min(511, max(0, k));
}

__device__ __forceinline__ void gather_addrs(float t, float px, float py, float pz,
                                             int sub, unsigned& c0, unsigned& c1, unsigned& c2) {
    int ix  = idx_w(t);
    c0 = (unsigned)(((0 * RES_H + idx_h(px)) * RES_W + ix) * (FEAT / 4)) + sub;
    c1 = (unsigned)(((1 * RES_H + idx_h(py)) * RES_W + ix) * (FEAT / 4)) + sub;
    c2 = (unsigned)(((2 * RES_H + idx_h(pz)) * RES_W + ix) * (FEAT / 4)) + sub;
}

// Gather load with evict_last L2 policy: pins the 12.6MB plane scratch in L2
// against the output write stream.
__device__ __forceinline__ uint2 ldg_el(const uint2* p, uint64_t pol) {
    uint2 v;
    asm volatile("ld.global.nc.L2::cache_hint.v2.u32 {%0,%1}, [%2], %3;"
                 : "=r"(v.x), "=r"(v.y) : "l"(p), "l"(pol));
    return v;
}

__device__ __forceinline__ float4 prod3(uint2 ua, uint2 ub, uint2 uc) {
    float2 a0 = __half22float2(*reinterpret_cast<__half2*>(&ua.x));
    float2 a1 = __half22float2(*reinterpret_cast<__half2*>(&ua.y));
    float2 b0 = __half22float2(*reinterpret_cast<__half2*>(&ub.x));
    float2 b1 = __half22float2(*reinterpret_cast<__half2*>(&ub.y));
    float2 c0f = __half22float2(*reinterpret_cast<__half2*>(&uc.x));
    float2 c1f = __half22float2(*reinterpret_cast<__half2*>(&uc.y));
    float4 r;
    r.x = __fmul_rn(__fmul_rn(a0.x, b0.x), c0f.x);
    r.y = __fmul_rn(__fmul_rn(a0.y, b0.y), c0f.y);
    r.z = __fmul_rn(__fmul_rn(a1.x, b1.x), c1f.x);
    r.w = __fmul_rn(__fmul_rn(a1.y, b1.y), c1f.y);
    return r;
}

// ---------------------------------------------------------------------------
// Kernel 2: gather + product + dual write. Block = 256 threads = 64 points,
// 2 pts/thread (MLP 6). Staging + index math before the PDL grid-sync.
// Output via __stcs (evict_first): the 256MB write stream self-evicts and
// leaves L2 holding the planes + inputs across graph replays (R13 showed
// evict_normal stores flush L2 and blow up the next replay's transpose).
// ---------------------------------------------------------------------------
__global__ void __launch_bounds__(256)
displacement_kernel(const float* __restrict__ pts,
                    const float* __restrict__ tim,
                    float* __restrict__ out) {
    __shared__ float s_p[192];  // pts for 64 points
    __shared__ float s_t[64];   // tim for 64 points

    int tid  = threadIdx.x;
    int base = blockIdx.x * 64;

    if (tid < 192)  s_p[tid]       = pts[base * 3 + tid];
    else            s_t[tid - 192] = tim[base + (tid - 192)];
    __syncthreads();

    int il  = tid >> 3;      // local point 0..31 (pair partner: il+32)
    int sub = tid & 7;
    int jl  = il + 32;
    int i0  = base + il;
    int i1  = base + jl;     // only i1 can be NPTS-1

    float t0  = __fadd_rn(__fmul_rn(s_t[il], 2.0f), -1.0f);
    float px0 = __fmul_rn(-s_p[3 * il + 0], INV_BOUNDS);
    float py0 = __fmul_rn(-s_p[3 * il + 1], INV_BOUNDS);
    float pz0 = __fmul_rn(-s_p[3 * il + 2], INV_BOUNDS);
    float t1  = __fadd_rn(__fmul_rn(s_t[jl], 2.0f), -1.0f);
    float px1 = __fmul_rn(-s_p[3 * jl + 0], INV_BOUNDS);
    float py1 = __fmul_rn(-s_p[3 * jl + 1], INV_BOUNDS);
    float pz1 = __fmul_rn(-s_p[3 * jl + 2], INV_BOUNDS);

    unsigned a0, a1, a2, b0, b1, b2;
    gather_addrs(t0, px0, py0, pz0, sub, a0, a1, a2);
    gather_addrs(t1, px1, py1, pz1, sub, b0, b1, b2);

    uint64_t pol;
    asm("createpolicy.fractional.L2::evict_last.b64 %0, 1.0;" : "=l"(pol));

    // Wait for the transpose's global writes to be visible, then gather.
    cudaGridDependencySynchronize();

    const uint2* gbase = reinterpret_cast<const uint2*>(g_T16);
    uint2 va0 = ldg_el(gbase + a0, pol);
    uint2 va1 = ldg_el(gbase + a1, pol);
    uint2 va2 = ldg_el(gbase + a2, pol);
    uint2 vb0 = ldg_el(gbase + b0, pol);
    uint2 vb1 = ldg_el(gbase + b1, pol);
    uint2 vb2 = ldg_el(gbase + b2, pol);

    float4 r0 = prod3(va0, va1, va2);
    float4 r1 = prod3(vb0, vb1, vb2);
    float4 r1A = r1, r1B = r1;

    if (i1 == NPTS - 1) {
        // data_shift subtracts TSTEP from ALL 4 components of the last row only
        unsigned s0, s1, s2;
        gather_addrs(__fadd_rn(t1, -TSTEP), __fadd_rn(px1, -TSTEP),
                     __fadd_rn(py1, -TSTEP), __fadd_rn(pz1, -TSTEP), sub, s0, s1, s2);
        float4 r2 = prod3(ldg_el(gbase + s0, pol), ldg_el(gbase + s1, pol),
                          ldg_el(gbase + s2, pol));
        bool cond = __fadd_rn(px1, TSTEP) > 1.0f;   // data[-1,0] + TIME_STEP > 1.0
        r1A = cond ? r2 : r1;
        r1B = cond ? r1 : r2;
    }

    // feature_A at [0, N*F), feature_B at [N*F, 2*N*F).
    float4* o = reinterpret_cast<float4*>(out);
    size_t row0 = (size_t)i0 * 8 + sub;
    size_t row1 = (size_t)i1 * 8 + sub;
    __stcs(o + row0, r0);
    __stcs(o + row1, r1A);
    __stcs(o + (size_t)NPTS * 8 + row0, r0);
    __stcs(o + (size_t)NPTS * 8 + row1, r1B);
}

extern "C" void kernel_launch(void* const* d_in, const int* in_sizes, int n_in,
                              void* d_out, int out_size) {
    const float* pts  = (const float*)d_in[0];
    const float* tim  = (const float*)d_in[1];
    const float* p0   = (const float*)d_in[2];
    const float* p1   = (const float*)d_in[3];
    const float* p2   = (const float*)d_in[4];
    float* out = (float*)d_out;

    // 1) transpose+convert planes to [H,W,F] fp16 (1 block per plane-row)
    transpose_planes<<<3 * RES_H, 256>>>(p0, p1, p2);

    // 2) main kernel launched with PDL so its launch+preamble overlap the
    //    transpose tail; it grid-syncs before touching g_T16.
    cudaLaunchAttribute attrs[1];
    attrs[0].id = cudaLaunchAttributeProgrammaticStreamSerialization;
    attrs[0].val.programmaticStreamSerializationAllowed = 1;

    cudaLaunchConfig_t cfg = {};
    cfg.gridDim  = dim3(NPTS / 64);
    cfg.blockDim = dim3(256);
    cfg.dynamicSmemBytes = 0;
    cfg.stream = 0;
    cfg.attrs = attrs;
    cfg.numAttrs = 1;
    cudaLaunchKernelEx(&cfg, displacement_kernel, pts, tim, out);
}

// round 16
// speedup vs baseline: 1.0690x; 1.0334x over previous
#include <cuda_runtime.h>
#include <cuda_bf16.h>
#include <cuda_fp16.h>
#include <cstdint>

// Problem constants
#define NPTS   1000000
#define FEAT   32
#define RES_H  512
#define RES_W  128
#define TSTEP  (1.0f/256.0f)   // 1/(2*RES_W), exactly representable
// XLA rewrites (-pts / 1.6f) as (-pts * (1/1.6f)); 1/1.6f rounds to exactly 0.625f.
#define INV_BOUNDS 0.625f

// Transposed fp16 planes: [plane][h][w][f] — 3*512*128*32*2 = 12.6 MB, L2-resident.
__device__ __half g_T16[3 * RES_H * RES_W * FEAT];

// evict_last policy register (uniform).
__device__ __forceinline__ uint64_t make_el_policy() {
    uint64_t pol;
    asm("createpolicy.fractional.L2::evict_last.b64 %0, 1.0;" : "=l"(pol));
    return pol;
}

// float4 load with evict_last L2 policy (persistent data: source planes).
__device__ __forceinline__ float4 ldg_el_f4(const float4* p, uint64_t pol) {
    float4 v;
    asm volatile("ld.global.nc.L2::cache_hint.v4.f32 {%0,%1,%2,%3}, [%4], %5;"
                 : "=f"(v.x), "=f"(v.y), "=f"(v.z), "=f"(v.w) : "l"(p), "l"(pol));
    return v;
}

// uint2 (4 halves) load with evict_last L2 policy (persistent data: scratch).
__device__ __forceinline__ uint2 ldg_el(const uint2* p, uint64_t pol) {
    uint2 v;
    asm volatile("ld.global.nc.L2::cache_hint.v2.u32 {%0,%1}, [%2], %3;"
                 : "=r"(v.x), "=r"(v.y) : "l"(p), "l"(pol));
    return v;
}

// ---------------------------------------------------------------------------
// Kernel 1: transpose+convert each plane [F,H,W] fp32 -> [H,W,F] fp16.
// One block per (plane, h): 1536 blocks x 256 threads. Source reads carry
// evict_last policy so the 25MB of fp32 planes stay L2-resident across graph
// replays (they were being eroded by the 256MB output stream). PDL trigger
// fires after the global writes are issued.
// ---------------------------------------------------------------------------
__global__ void __launch_bounds__(256)
transpose_planes(const float* __restrict__ p0,
                 const float* __restrict__ p1,
                 const float* __restrict__ p2) {
    __shared__ float tile[32][129];
    int b   = blockIdx.x;
    int h   = b & 511;
    int pl  = b >> 9;
    const float* src = (pl == 0) ? p0 : ((pl == 1) ? p1 : p2);
    int tid = threadIdx.x;
    uint64_t pol = make_el_policy();

    // Read 32f x 128w as float4: 1024 float4 per block, 4 per thread.
    const float4* src4 = reinterpret_cast<const float4*>(src);
    #pragma unroll
    for (int k = 0; k < 4; k++) {
        int idx4 = tid + 256 * k;
        int f  = idx4 >> 5;        // 32 float4 per row
        int w4 = idx4 & 31;
        float4 v = ldg_el_f4(src4 + (size_t)f * (RES_H * RES_W / 4) + h * (RES_W / 4) + w4, pol);
        tile[f][4 * w4 + 0] = v.x;
        tile[f][4 * w4 + 1] = v.y;
        tile[f][4 * w4 + 2] = v.z;
        tile[f][4 * w4 + 3] = v.w;
    }
    __syncthreads();

    __half2* dst = reinterpret_cast<__half2*>(g_T16) + (size_t)(pl * RES_H + h) * (RES_W * FEAT / 2);
    #pragma unroll
    for (int k = 0; k < 8; k++) {
        int idx2 = tid + 256 * k;
        int w  = idx2 >> 4;
        int fp = idx2 & 15;
        dst[idx2] = __floats2half2_rn(tile[2 * fp][w], tile[2 * fp + 1][w]);
    }
    // Allow the dependent (main) kernel to start launching.
    cudaTriggerProgrammaticLaunchCompletion();
}

// ---------------------------------------------------------------------------
// Index math: IEEE round-to-nearest ops, round-half-even conversion.
// ---------------------------------------------------------------------------
__device__ __forceinline__ int idx_w(float c) {
    float v = __fmul_rn(__fmul_rn(__fadd_rn(c, 1.0f), 0.5f), 127.0f);
    int k = __float2int_rn(v);
    return min(127, max(0, k));
}
__device__ __forceinline__ int idx_h(float c) {
    float v = __fmul_rn(__fmul_rn(__fadd_rn(c, 1.0f), 0.5f), 511.0f);
    int k = __float2int_rn(v);
    return min(511, max(0, k));
}

__device__ __forceinline__ void gather_addrs(float t, float px, float py, float pz,
                                             int sub, unsigned& c0, unsigned& c1, unsigned& c2) {
    int ix  = idx_w(t);
    c0 = (unsigned)(((0 * RES_H + idx_h(px)) * RES_W + ix) * (FEAT / 4)) + sub;
    c1 = (unsigned)(((1 * RES_H + idx_h(py)) * RES_W + ix) * (FEAT / 4)) + sub;
    c2 = (unsigned)(((2 * RES_H + idx_h(pz)) * RES_W + ix) * (FEAT / 4)) + sub;
}

__device__ __forceinline__ float4 prod3(uint2 ua, uint2 ub, uint2 uc) {
    float2 a0 = __half22float2(*reinterpret_cast<__half2*>(&ua.x));
    float2 a1 = __half22float2(*reinterpret_cast<__half2*>(&ua.y));
    float2 b0 = __half22float2(*reinterpret_cast<__half2*>(&ub.x));
    float2 b1 = __half22float2(*reinterpret_cast<__half2*>(&ub.y));
    float2 c0f = __half22float2(*reinterpret_cast<__half2*>(&uc.x));
    float2 c1f = __half22float2(*reinterpret_cast<__half2*>(&uc.y));
    float4 r;
    r.x = __fmul_rn(__fmul_rn(a0.x, b0.x), c0f.x);
    r.y = __fmul_rn(__fmul_rn(a0.y, b0.y), c0f.y);
    r.z = __fmul_rn(__fmul_rn(a1.x, b1.x), c1f.x);
    r.w = __fmul_rn(__fmul_rn(a1.y, b1.y), c1f.y);
    return r;
}

// ---------------------------------------------------------------------------
// Kernel 2: gather + product + dual write. Block = 256 threads = 64 points,
// 2 pts/thread (MLP 6). Staging + index math before the PDL grid-sync.
// Gathers: evict_last (pin scratch). Output: __stcs evict_first (self-evicting
// stream; protects L2 residency of persistent data across replays).
// ---------------------------------------------------------------------------
__global__ void __launch_bounds__(256)
displacement_kernel(const float* __restrict__ pts,
                    const float* __restrict__ tim,
                    float* __restrict__ out) {
    __shared__ float s_p[192];  // pts for 64 points
    __shared__ float s_t[64];   // tim for 64 points

    int tid  = threadIdx.x;
    int base = blockIdx.x * 64;

    if (tid < 192)  s_p[tid]       = pts[base * 3 + tid];
    else            s_t[tid - 192] = tim[base + (tid - 192)];
    __syncthreads();

    int il  = tid >> 3;      // local point 0..31 (pair partner: il+32)
    int sub = tid & 7;
    int jl  = il + 32;
    int i0  = base + il;
    int i1  = base + jl;     // only i1 can be NPTS-1

    float t0  = __fadd_rn(__fmul_rn(s_t[il], 2.0f), -1.0f);
    float px0 = __fmul_rn(-s_p[3 * il + 0], INV_BOUNDS);
    float py0 = __fmul_rn(-s_p[3 * il + 1], INV_BOUNDS);
    float pz0 = __fmul_rn(-s_p[3 * il + 2], INV_BOUNDS);
    float t1  = __fadd_rn(__fmul_rn(s_t[jl], 2.0f), -1.0f);
    float px1 = __fmul_rn(-s_p[3 * jl + 0], INV_BOUNDS);
    float py1 = __fmul_rn(-s_p[3 * jl + 1], INV_BOUNDS);
    float pz1 = __fmul_rn(-s_p[3 * jl + 2], INV_BOUNDS);

    unsigned a0, a1, a2, b0, b1, b2;
    gather_addrs(t0, px0, py0, pz0, sub, a0, a1, a2);
    gather_addrs(t1, px1, py1, pz1, sub, b0, b1, b2);

    uint64_t pol = make_el_policy();

    // Wait for the transpose's global writes to be visible, then gather.
    cudaGridDependencySynchronize();

    const uint2* gbase = reinterpret_cast<const uint2*>(g_T16);
    uint2 va0 = ldg_el(gbase + a0, pol);
    uint2 va1 = ldg_el(gbase + a1, pol);
    uint2 va2 = ldg_el(gbase + a2, pol);
    uint2 vb0 = ldg_el(gbase + b0, pol);
    uint2 vb1 = ldg_el(gbase + b1, pol);
    uint2 vb2 = ldg_el(gbase + b2, pol);

    float4 r0 = prod3(va0, va1, va2);
    float4 r1 = prod3(vb0, vb1, vb2);
    float4 r1A = r1, r1B = r1;

    if (i1 == NPTS - 1) {
        // data_shift subtracts TSTEP from ALL 4 components of the last row only
        unsigned s0, s1, s2;
        gather_addrs(__fadd_rn(t1, -TSTEP), __fadd_rn(px1, -TSTEP),
                     __fadd_rn(py1, -TSTEP), __fadd_rn(pz1, -TSTEP), sub, s0, s1, s2);
        float4 r2 = prod3(ldg_el(gbase + s0, pol), ldg_el(gbase + s1, pol),
                          ldg_el(gbase + s2, pol));
        bool cond = __fadd_rn(px1, TSTEP) > 1.0f;   // data[-1,0] + TIME_STEP > 1.0
        r1A = cond ? r2 : r1;
        r1B = cond ? r1 : r2;
    }

    // feature_A at [0, N*F), feature_B at [N*F, 2*N*F).
    float4* o = reinterpret_cast<float4*>(out);
    size_t row0 = (size_t)i0 * 8 + sub;
    size_t row1 = (size_t)i1 * 8 + sub;
    __stcs(o + row0, r0);
    __stcs(o + row1, r1A);
    __stcs(o + (size_t)NPTS * 8 + row0, r0);
    __stcs(o + (size_t)NPTS * 8 + row1, r1B);
}

extern "C" void kernel_launch(void* const* d_in, const int* in_sizes, int n_in,
                              void* d_out, int out_size) {
    const float* pts  = (const float*)d_in[0];
    const float* tim  = (const float*)d_in[1];
    const float* p0   = (const float*)d_in[2];
    const float* p1   = (const float*)d_in[3];
    const float* p2   = (const float*)d_in[4];
    float* out = (float*)d_out;

    // 1) transpose+convert planes to [H,W,F] fp16 (1 block per plane-row)
    transpose_planes<<<3 * RES_H, 256>>>(p0, p1, p2);

    // 2) main kernel launched with PDL so its launch+preamble overlap the
    //    transpose tail; it grid-syncs before touching g_T16.
    cudaLaunchAttribute attrs[1];
    attrs[0].id = cudaLaunchAttributeProgrammaticStreamSerialization;
    attrs[0].val.programmaticStreamSerializationAllowed = 1;

    cudaLaunchConfig_t cfg = {};
    cfg.gridDim  = dim3(NPTS / 64);
    cfg.blockDim = dim3(256);
    cfg.dynamicSmemBytes = 0;
    cfg.stream = 0;
    cfg.attrs = attrs;
    cfg.numAttrs = 1;
    cudaLaunchKernelEx(&cfg, displacement_kernel, pts, tim, out);
}